// round 15
// baseline (speedup 1.0000x reference)
#include <cuda_runtime.h>
#include <cstdint>

// Fixed shapes: B=32, T=1024, D=1024. All GEMM paths are dead code:
// softmax over a singleton axis => every attention weight == 1.0, so
//   context[b,d] = sum_t values[b,t,d],  aw = 1.0,  cov[b,t] = t.
#define BB 32
#define TT 1024
#define DD 1024
#define D4 256                       // float4 per row (4KB rows)
#define NCHUNK 16                    // chunks per batch (CTAs per batch)
#define TC (TT / NCHUNK)             // 64 rows per chunk (256KB contiguous)
#define THREADS 512                  // 2 x 256: two 32-row half-streams per CTA

// Output layout (98304 floats):
//   [0, B*D)             context   (zeroed in-grid, TMA-bulk-reduce accumulated)
//   [B*D, B*D+B*T)       attention_weights (all 1.0)
//   [B*D+B*T, end)       coverage (cov[b,t] = t)

// Per-batch monotonic tickets (zero-init at load; epoch arithmetic keeps them
// replay-safe without resets). Stride 32 -> one counter per 128B line.
__device__ unsigned int g_cnt[BB * 32];

__device__ __forceinline__ uint32_t smem_u32(const void* p) {
    uint32_t a;
    asm("{ .reg .u64 t; cvta.to.shared.u64 t, %1; cvt.u32.u64 %0, t; }"
        : "=r"(a) : "l"(p));
    return a;
}

// ---- Single kernel: in-grid zero + stream + TMA bulk-reduce (fan-in 16) ----
// Same stream character as the proven 6.27 TB/s shape (thread-per-float4-
// column over 32 contiguous rows, 8-deep independent __ldcs loads), but two
// half-streams share one CTA -> ONE bulk-reduce per 256KB instead of per
// 128KB: the end-of-kernel L2 RMW burst and the zero-handshake both halve.
__global__ __launch_bounds__(THREADS) void stage1_kernel(const float4* __restrict__ vals,
                                                         float* __restrict__ out) {
    __shared__ float4 part[D4];      // 4KB combined partial
    __shared__ float4 half1[D4];     // 4KB half-1 partial
    __shared__ unsigned int s_ticket;

    const int c   = blockIdx.x;      // 0..15 chunk
    const int b   = blockIdx.y;      // 0..31 batch
    const int tid = threadIdx.x;     // 0..511
    const int col = tid & (D4 - 1);  // 0..255 (float4 column)
    const int h   = tid >> 8;        // 0..1 (32-row half)

    // ---- Prologue: zero this CTA's 256B share of context, take a ticket ----
    if (tid < 16) {
        float4* z = reinterpret_cast<float4*>(out + (size_t)b * DD + (size_t)c * 64);
        z[tid] = make_float4(0.f, 0.f, 0.f, 0.f);
        __threadfence();             // zeros visible before our ticket
    }
    __syncthreads();
    if (tid == 0) s_ticket = atomicAdd(&g_cnt[b * 32], 1u);

    // ---- Stream: each half covers 32 contiguous rows (128KB), 8-deep loads ----
    const float4* __restrict__ p =
        vals + ((size_t)b * TT + (size_t)c * TC + (size_t)h * 32) * D4 + col;

    float x = 0.f, y = 0.f, z = 0.f, w = 0.f;
#pragma unroll
    for (int i = 0; i < 4; ++i) {    // 4 x 8 = 32 rows
        float4 v0 = __ldcs(&p[0 * (size_t)D4]);
        float4 v1 = __ldcs(&p[1 * (size_t)D4]);
        float4 v2 = __ldcs(&p[2 * (size_t)D4]);
        float4 v3 = __ldcs(&p[3 * (size_t)D4]);
        float4 v4 = __ldcs(&p[4 * (size_t)D4]);
        float4 v5 = __ldcs(&p[5 * (size_t)D4]);
        float4 v6 = __ldcs(&p[6 * (size_t)D4]);
        float4 v7 = __ldcs(&p[7 * (size_t)D4]);
        p += 8 * (size_t)D4;
        x += v0.x; y += v0.y; z += v0.z; w += v0.w;
        x += v1.x; y += v1.y; z += v1.z; w += v1.w;
        x += v2.x; y += v2.y; z += v2.z; w += v2.w;
        x += v3.x; y += v3.y; z += v3.z; w += v3.w;
        x += v4.x; y += v4.y; z += v4.z; w += v4.w;
        x += v5.x; y += v5.y; z += v5.z; w += v5.w;
        x += v6.x; y += v6.y; z += v6.z; w += v6.w;
        x += v7.x; y += v7.y; z += v7.z; w += v7.w;
    }
    if (h == 1) half1[col] = make_float4(x, y, z, w);

    // aw/cov fill: 512 blocks x 16 float4 per array (hidden in the stream).
    const int blk = b * NCHUNK + c;  // 0..511
    if (tid >= 320 && tid < 336) {
        float4* aw4 = reinterpret_cast<float4*>(out + BB * DD);
        aw4[blk * 16 + (tid - 320)] = make_float4(1.f, 1.f, 1.f, 1.f);
    } else if (tid >= 352 && tid < 368) {
        float4* cov4 = reinterpret_cast<float4*>(out + BB * DD + BB * TT);
        const int q = blk * 16 + (tid - 352);    // float4 index into [B,T]
        const int t0 = (q * 4) & (TT - 1);
        cov4[q] = make_float4((float)t0, (float)(t0 + 1), (float)(t0 + 2), (float)(t0 + 3));
    }

    __syncthreads();                 // stream done; half1 in smem

    if (h == 0) {                    // combine halves (post-stream, no drain cost)
        float4 o = half1[col];
        part[col] = make_float4(x + o.x, y + o.y, z + o.z, w + o.w);
    }
    __syncthreads();                 // part complete; s_ticket visible

    if (tid == 0) {
        // All 16 CTAs of this batch (this epoch) must have zeroed their share.
        // ~20us into the kernel this is a single satisfied load, not a spin.
        const unsigned int target = (s_ticket / NCHUNK + 1u) * NCHUNK;
        while (*(volatile unsigned int*)&g_cnt[b * 32] < target) {}
        __threadfence();             // acquire: peer zeros visible
        // Order generic stores (smem partial + global zeros) before async proxy.
        asm volatile("fence.proxy.async;" ::: "memory");

        float* dst = out + (size_t)b * DD;       // context row for this batch
        asm volatile(
            "cp.reduce.async.bulk.global.shared::cta.bulk_group.add.f32 "
            "[%0], [%1], %2;"
            :: "l"(dst), "r"(smem_u32(part)), "r"((uint32_t)(D4 * sizeof(float4)))
            : "memory");
        asm volatile("cp.async.bulk.commit_group;" ::: "memory");
        asm volatile("cp.async.bulk.wait_group 0;" ::: "memory");  // R14 lesson
    }
}

extern "C" void kernel_launch(void* const* d_in, const int* in_sizes, int n_in,
                              void* d_out, int out_size) {
    // Inputs: query, values, W1, b1, W2, b2, W3, b3, V, bV
    const float4* values = (const float4*)d_in[1];
    float* out = (float*)d_out;

    dim3 grid1(NCHUNK, BB);                      // 512 blocks x 512 threads
    stage1_kernel<<<grid1, THREADS>>>(values, out);
}